// round 10
// baseline (speedup 1.0000x reference)
#include <cuda_runtime.h>
#include <cuda_bf16.h>
#include <math.h>
#include <stdint.h>

typedef unsigned long long ull;

#define BSZ 2
#define SEQ 2048
#define DM  1024
#define HN  16
#define DKH 64
#define RR  (BSZ*SEQ)   // 4096 rows
#define NP  (DM/2)      // 512 rotary pairs
#define K2  (2*DM)      // 2048 physical K (hi|lo)
#define K2B (K2*2)      // 4096 bytes/row

// ---------------------------------------------------------------------------
// Scratch (device globals: allocation is forbidden)
// ---------------------------------------------------------------------------
__device__ float g_V[RR*DM];
__device__ float g_theta[NP];
__device__ float g_cos[SEQ*NP];
__device__ float g_sin[SEQ*NP];
__device__ __nv_bfloat16 g_A3[3*RR*K2];   // q,k,v split [row][hi|lo]
__device__ __nv_bfloat16 g_W4[4*DM*K2];   // Wq,Wk,Wv,Wo split [col][hi|lo]
__device__ __nv_bfloat16 g_AY[RR*K2];     // attention output split [row][hi|lo]
// attention operands: [bh][s][64] (Q/K) and [bh][d][s] (V transposed)
__device__ __nv_bfloat16 g_Qh[BSZ*HN*SEQ*DKH];
__device__ __nv_bfloat16 g_Ql[BSZ*HN*SEQ*DKH];
__device__ __nv_bfloat16 g_Kh[BSZ*HN*SEQ*DKH];
__device__ __nv_bfloat16 g_Kl[BSZ*HN*SEQ*DKH];
__device__ __nv_bfloat16 g_Vth[BSZ*HN*DKH*SEQ];
__device__ __nv_bfloat16 g_Vtl[BSZ*HN*DKH*SEQ];

// ---------------------------------------------------------------------------
// PTX helpers
// ---------------------------------------------------------------------------
static __device__ __forceinline__ uint32_t smem_u32(const void* p) {
    uint32_t a;
    asm("{ .reg .u64 t; cvta.to.shared.u64 t, %1; cvt.u32.u64 %0, t; }"
        : "=r"(a) : "l"(p));
    return a;
}
#define CP16(dst, src) \
    asm volatile("cp.async.cg.shared.global [%0], [%1], 16;" \
                 :: "r"(dst), "l"(src) : "memory")
#define CP_COMMIT() asm volatile("cp.async.commit_group;" ::: "memory")
#define CP_WAIT0()  asm volatile("cp.async.wait_group 0;" ::: "memory")
#define CP_WAIT1()  asm volatile("cp.async.wait_group 1;" ::: "memory")

static __device__ __forceinline__ void ldsm4(uint32_t* r, uint32_t addr) {
    asm volatile("ldmatrix.sync.aligned.m8n8.x4.shared.b16 {%0,%1,%2,%3}, [%4];"
                 : "=r"(r[0]), "=r"(r[1]), "=r"(r[2]), "=r"(r[3]) : "r"(addr));
}
static __device__ __forceinline__ void mma16816(float* c, const uint32_t* a,
                                                uint32_t b0, uint32_t b1) {
    asm volatile(
        "mma.sync.aligned.m16n8k16.row.col.f32.bf16.bf16.f32 "
        "{%0,%1,%2,%3}, {%4,%5,%6,%7}, {%8,%9}, {%0,%1,%2,%3};"
        : "+f"(c[0]), "+f"(c[1]), "+f"(c[2]), "+f"(c[3])
        : "r"(a[0]), "r"(a[1]), "r"(a[2]), "r"(a[3]), "r"(b0), "r"(b1));
}
static __device__ __forceinline__ __nv_bfloat162 split_hi2(float x, float y,
                                                           __nv_bfloat162& lo) {
    __nv_bfloat16 hx = __float2bfloat16(x), hy = __float2bfloat16(y);
    lo = __nv_bfloat162{__float2bfloat16(x - __bfloat162float(hx)),
                        __float2bfloat16(y - __bfloat162float(hy))};
    return __nv_bfloat162{hx, hy};
}

// ---------------------------------------------------------------------------
// RoPE tables
// ---------------------------------------------------------------------------
__global__ void theta_kernel() {
    int i = threadIdx.x;
    if (i < NP)
        g_theta[i] = (float)pow(10000.0, -2.0 * (double)i / (double)DM);
}

__global__ void __launch_bounds__(256) table_kernel() {
    int idx = blockIdx.x * 256 + threadIdx.x;
    if (idx < SEQ * NP) {
        int pos = idx >> 9;
        int i   = idx & (NP - 1);
        float ang = (float)pos * g_theta[i];
        float s, c;
        sincosf(ang, &s, &c);
        g_cos[idx] = c;
        g_sin[idx] = s;
    }
}

// ---------------------------------------------------------------------------
// Splits: write [hi | lo] (K2) — the GEMM k-map realizes hi|lo|hi / hi|hi|lo
// ---------------------------------------------------------------------------
__global__ void __launch_bounds__(256) split_a3_kernel(
    const float* __restrict__ q, const float* __restrict__ k,
    const float* __restrict__ v) {
    int idx = blockIdx.x * 256 + threadIdx.x;
    const float* X = blockIdx.y == 0 ? q : (blockIdx.y == 1 ? k : v);
    int row = idx >> 10, kk = idx & (DM - 1);
    float x = X[idx];
    __nv_bfloat16 hi = __float2bfloat16(x);
    __nv_bfloat16 lo = __float2bfloat16(x - __bfloat162float(hi));
    __nv_bfloat16* O = g_A3 + (size_t)blockIdx.y * (RR * K2);
    size_t base = (size_t)row * K2;
    O[base + kk] = hi;
    O[base + DM + kk] = lo;
}

__global__ void __launch_bounds__(256) split_w4_kernel(
    const float* __restrict__ Wq, const float* __restrict__ Wk,
    const float* __restrict__ Wv, const float* __restrict__ Wo) {
    int idx = blockIdx.x * 256 + threadIdx.x;
    const float* X = blockIdx.y == 0 ? Wq :
                     (blockIdx.y == 1 ? Wk : (blockIdx.y == 2 ? Wv : Wo));
    int row = idx >> 10, kk = idx & (DM - 1);
    float x = X[idx];
    __nv_bfloat16 hi = __float2bfloat16(x);
    __nv_bfloat16 lo = __float2bfloat16(x - __bfloat162float(hi));
    __nv_bfloat16* O = g_W4 + (size_t)blockIdx.y * (DM * K2);
    size_t base = (size_t)row * K2;
    O[base + kk] = hi;
    O[base + DM + kk] = lo;
}

// V: transpose + split into [bh][d][s]
__global__ void __launch_bounds__(256) v_prep_kernel() {
    __shared__ float t[32][33];
    int s0 = blockIdx.x * 32, d0 = blockIdx.y * 32, b = blockIdx.z;
    int tx = threadIdx.x, ty = threadIdx.y;   // block (32, 8)
#pragma unroll
    for (int r = 0; r < 4; r++) {
        int sl = ty + r * 8;
        t[sl][tx] = g_V[(size_t)(b * SEQ + s0 + sl) * DM + d0 + tx];
    }
    __syncthreads();
    int head = d0 >> 6;
    int bh = b * HN + head;
#pragma unroll
    for (int r = 0; r < 4; r++) {
        int dl = ty + r * 8;
        float x = t[tx][dl];
        __nv_bfloat16 hi = __float2bfloat16(x);
        __nv_bfloat16 lo = __float2bfloat16(x - __bfloat162float(hi));
        size_t o = ((size_t)bh * 64 + ((d0 & 63) + dl)) * SEQ + s0 + tx;
        g_Vth[o] = hi;
        g_Vtl[o] = lo;
    }
}

// ---------------------------------------------------------------------------
// HMMA GEMM, logical K=3072 over physical [hi|lo] via k-chunk map.
// 128x128 tile, 8 warps, BK=64, 3-stage cp.async pipeline, one sync/tile.
// A-map (hi,lo,hi):  aoff(kt) = (kt<32 ? kt : kt-32)*128
// W-map (hi,hi,lo):  woff(kt) = (kt<16 ? kt : kt-16)*128
// ---------------------------------------------------------------------------
#define NKIT 48                 // 3072 / 64
#define STAGE_A 16384           // 128 rows x 128 B
#define STAGE_SZ (2 * STAGE_A)  // A + B
#define GEMM_SMEM (3 * STAGE_SZ)  // 98304

static __device__ __forceinline__ uint32_t a_koff(int kt) {
    return (uint32_t)((kt < 32 ? kt : kt - 32) * 128);
}
static __device__ __forceinline__ uint32_t w_koff(int kt) {
    return (uint32_t)((kt < 16 ? kt : kt - 16) * 128);
}

// Shared mainloop: accumulates acc for tile (row0, col0).
static __device__ __forceinline__ void gemm_mainloop(
    const __nv_bfloat16* A, const __nv_bfloat16* W, char* sm,
    int row0, int col0, float acc[2][8][4]) {
    const uint32_t sb = smem_u32(sm);
    const int tid = threadIdx.x;
    const int lane = tid & 31, wid = tid >> 5;
    const int wm = wid & 3, wn = wid >> 2;

    // global->smem: thread loads row lr, 4 chunks starting at c0 (A and B)
    const int lr = tid >> 1;
    const int c0 = (tid & 1) * 4;
    const int ssel = lr & 7;
    const char* Ag = (const char*)A + (size_t)(row0 + lr) * K2B;
    const char* Wg = (const char*)W + (size_t)(col0 + lr) * K2B;
    uint32_t sdA[4], sdB[4];
#pragma unroll
    for (int i = 0; i < 4; i++) {
        sdA[i] = sb + (uint32_t)(lr * 128 + (((c0 + i) ^ ssel) * 16));
        sdB[i] = sdA[i] + STAGE_A;
    }

    // ldmatrix lane components
    const int alr = (lane & 7) + ((lane >> 3) & 1) * 8;
    const int ag2 = lane >> 4;
    const int asel = alr & 7;
    const int nlr = (lane & 7) + ((lane >> 4) & 1) * 8;
    const int bg2 = (lane >> 3) & 1;
    const int bsel = nlr & 7;

    uint32_t arow[2], brow[4];
#pragma unroll
    for (int mi = 0; mi < 2; mi++)
        arow[mi] = (uint32_t)((wm * 32 + mi * 16 + alr) * 128);
#pragma unroll
    for (int nj = 0; nj < 4; nj++)
        brow[nj] = (uint32_t)(STAGE_A + (wn * 64 + nj * 16 + nlr) * 128);

#pragma unroll
    for (int mi = 0; mi < 2; mi++)
#pragma unroll
        for (int ni = 0; ni < 8; ni++)
#pragma unroll
            for (int j = 0; j < 4; j++) acc[mi][ni][j] = 0.f;

    // prologue: stage kt=0,1
#pragma unroll
    for (int p = 0; p < 2; p++) {
        const uint32_t stb = (uint32_t)p * STAGE_SZ;
        const uint32_t ao = a_koff(p), wo = w_koff(p);
#pragma unroll
        for (int i = 0; i < 4; i++) {
            CP16(sdA[i] + stb, Ag + ao + (c0 + i) * 16);
            CP16(sdB[i] + stb, Wg + wo + (c0 + i) * 16);
        }
        CP_COMMIT();
    }

    int st = 0;       // stage of tile kt
    for (int kt = 0; kt < NKIT; kt++) {
        if (kt == NKIT - 1) CP_WAIT0(); else CP_WAIT1();
        __syncthreads();   // tile kt visible; all warps done with tile kt-1
        if (kt + 2 < NKIT) {
            int stn = st + 2; if (stn >= 3) stn -= 3;
            const uint32_t stb = (uint32_t)stn * STAGE_SZ;
            const uint32_t ao = a_koff(kt + 2), wo = w_koff(kt + 2);
#pragma unroll
            for (int i = 0; i < 4; i++) {
                CP16(sdA[i] + stb, Ag + ao + (c0 + i) * 16);
                CP16(sdB[i] + stb, Wg + wo + (c0 + i) * 16);
            }
            CP_COMMIT();
        }
        const uint32_t stb = sb + (uint32_t)st * STAGE_SZ;
#pragma unroll
        for (int ks = 0; ks < 4; ks++) {
            const uint32_t acs = (uint32_t)(((ks * 2 + ag2) ^ asel) * 16);
            const uint32_t bcs = (uint32_t)(((ks * 2 + bg2) ^ bsel) * 16);
            uint32_t a[2][4];
#pragma unroll
            for (int mi = 0; mi < 2; mi++)
                ldsm4(a[mi], stb + arow[mi] + acs);
#pragma unroll
            for (int nj = 0; nj < 4; nj++) {
                uint32_t b[4];
                ldsm4(b, stb + brow[nj] + bcs);
                mma16816(acc[0][2 * nj + 0], a[0], b[0], b[1]);
                mma16816(acc[0][2 * nj + 1], a[0], b[2], b[3]);
                mma16816(acc[1][2 * nj + 0], a[1], b[0], b[1]);
                mma16816(acc[1][2 * nj + 1], a[1], b[2], b[3]);
            }
        }
        if (++st >= 3) st = 0;
    }
    __syncthreads();
}

__global__ void __launch_bounds__(256, 2) gemm_qkv_kernel() {
    extern __shared__ __align__(16) char smg[];
    const int z = blockIdx.z;
    const int row0 = blockIdx.y * 128, col0 = blockIdx.x * 128;
    const __nv_bfloat16* A = g_A3 + (size_t)z * (RR * K2);
    const __nv_bfloat16* W = g_W4 + (size_t)z * (DM * K2);

    float acc[2][8][4];
    gemm_mainloop(A, W, smg, row0, col0, acc);

    const int lane = threadIdx.x & 31, wid = threadIdx.x >> 5;
    const int wm = wid & 3, wn = wid >> 2;
    const int rbase = row0 + wm * 32 + (lane >> 2);
    const int cbase = col0 + wn * 64 + (lane & 3) * 2;

    if (z == 2) {   // V: plain fp32
#pragma unroll
        for (int mi = 0; mi < 2; mi++)
#pragma unroll
            for (int ni = 0; ni < 8; ni++) {
                const int r = rbase + mi * 16;
                const int c = cbase + ni * 8;
                *(float2*)&g_V[(size_t)r * DM + c] =
                    make_float2(acc[mi][ni][0], acc[mi][ni][1]);
                *(float2*)&g_V[(size_t)(r + 8) * DM + c] =
                    make_float2(acc[mi][ni][2], acc[mi][ni][3]);
            }
        return;
    }

    // Q/K: fused RoPE + hi/lo split into per-head layout
    __nv_bfloat16* Oh = z ? g_Kh : g_Qh;
    __nv_bfloat16* Ol = z ? g_Kl : g_Ql;
#pragma unroll
    for (int mi = 0; mi < 2; mi++) {
#pragma unroll
        for (int ni = 0; ni < 8; ni++) {
            const int c = cbase + ni * 8;       // even
            const int p = c >> 1;
            const int head = c >> 6, coff = c & 63;
#pragma unroll
            for (int hf = 0; hf < 2; hf++) {
                const int grow = rbase + mi * 16 + hf * 8;
                const int bb = grow >> 11, spos = grow & (SEQ - 1);
                const float cv = g_cos[spos * NP + p];
                const float sv = g_sin[spos * NP + p];
                const float x0 = acc[mi][ni][hf * 2];
                const float x1 = acc[mi][ni][hf * 2 + 1];
                const float ox = x0 * cv + x1 * sv;
                const float oy = x1 * cv - x0 * sv;
                __nv_bfloat162 lo2;
                __nv_bfloat162 hi2 = split_hi2(ox, oy, lo2);
                const size_t off =
                    ((size_t)(bb * HN + head) * SEQ + spos) * 64 + coff;
                *(__nv_bfloat162*)&Oh[off] = hi2;
                *(__nv_bfloat162*)&Ol[off] = lo2;
            }
        }
    }
}

__global__ void __launch_bounds__(256, 2) gemm_out_kernel(
    const float* __restrict__ bias, float* __restrict__ C) {
    extern __shared__ __align__(16) char smg[];
    const int row0 = blockIdx.y * 128, col0 = blockIdx.x * 128;
    const __nv_bfloat16* W = g_W4 + (size_t)3 * (DM * K2);

    float acc[2][8][4];
    gemm_mainloop(g_AY, W, smg, row0, col0, acc);

    const int lane = threadIdx.x & 31, wid = threadIdx.x >> 5;
    const int wm = wid & 3, wn = wid >> 2;
    const int rbase = row0 + wm * 32 + (lane >> 2);
    const int cbase = col0 + wn * 64 + (lane & 3) * 2;
#pragma unroll
    for (int mi = 0; mi < 2; mi++)
#pragma unroll
        for (int ni = 0; ni < 8; ni++) {
            const int r = rbase + mi * 16;
            const int c = cbase + ni * 8;
            const float b0 = bias[c], b1 = bias[c + 1];
            *(float2*)&C[(size_t)r * DM + c] =
                make_float2(acc[mi][ni][0] + b0, acc[mi][ni][1] + b1);
            *(float2*)&C[(size_t)(r + 8) * DM + c] =
                make_float2(acc[mi][ni][2] + b0, acc[mi][ni][3] + b1);
        }
}

// ---------------------------------------------------------------------------
// HMMA flash attention (R8-validated mainloop); epilogue writes g_AY [hi|lo].
// ---------------------------------------------------------------------------
#define PSTR 144
#define A_QH 0
#define A_QL (A_QH + 128*PSTR)
#define A_KH (A_QL + 128*PSTR)
#define A_KL (A_KH + 2*64*PSTR)
#define A_VH (A_KL + 2*64*PSTR)
#define A_VL (A_VH + 2*64*PSTR)
#define A_PH (A_VL + 2*64*PSTR)
#define A_PL (A_PH + 128*PSTR)
#define A_LS (A_PL + 128*PSTR)
#define ATTN_SMEM2 (A_LS + 2*128*4)
#define KVBUF (64*PSTR)

__global__ void __launch_bounds__(256) attn2_kernel() {
    extern __shared__ char sm2[];
    const uint32_t sb = smem_u32(sm2);
    float* LS = (float*)(sm2 + A_LS);

    const int tid = threadIdx.x;
    const int lane = tid & 31, wid = tid >> 5;
    const int wm = wid & 3, wn = wid >> 2;
    const int q0 = blockIdx.x * 128;
    const int bh = blockIdx.y;
    const int b = bh >> 4, h = bh & 15;

    const char* gQh = (const char*)g_Qh + ((size_t)bh * SEQ + q0) * 128;
    const char* gQl = (const char*)g_Ql + ((size_t)bh * SEQ + q0) * 128;
    const char* gKh = (const char*)g_Kh + (size_t)bh * SEQ * 128;
    const char* gKl = (const char*)g_Kl + (size_t)bh * SEQ * 128;
    const char* gVh = (const char*)g_Vth + (size_t)bh * 64 * (SEQ * 2);
    const char* gVl = (const char*)g_Vtl + (size_t)bh * 64 * (SEQ * 2);

    const int alr = (lane & 7) + ((lane >> 3) & 1) * 8;
    const int ag2 = lane >> 4;
    const int nlr = (lane & 7) + ((lane >> 4) & 1) * 8;
    const int bg2 = (lane >> 3) & 1;

    {
        const int row = tid >> 1, c0 = (tid & 1) * 4;
#pragma unroll
        for (int i = 0; i < 4; i++) {
            const int c = c0 + i;
            CP16(sb + A_QH + row * PSTR + c * 16, gQh + (size_t)row * 128 + c * 16);
            CP16(sb + A_QL + row * PSTR + c * 16, gQl + (size_t)row * 128 + c * 16);
        }
    }
    {
        const int row = tid >> 2, cc = (tid & 3) * 2;
#pragma unroll
        for (int i = 0; i < 2; i++) {
            const int c = cc + i;
            CP16(sb + A_KH + row * PSTR + c * 16, gKh + (size_t)row * 128 + c * 16);
            CP16(sb + A_KL + row * PSTR + c * 16, gKl + (size_t)row * 128 + c * 16);
            CP16(sb + A_VH + row * PSTR + c * 16, gVh + (size_t)row * (SEQ * 2) + c * 16);
            CP16(sb + A_VL + row * PSTR + c * 16, gVl + (size_t)row * (SEQ * 2) + c * 16);
        }
    }
    CP_COMMIT();

    float o[2][4][4];
#pragma unroll
    for (int mi = 0; mi < 2; mi++)
#pragma unroll
        for (int ni = 0; ni < 4; ni++)
#pragma unroll
            for (int j = 0; j < 4; j++) o[mi][ni][j] = 0.f;
    float ls[2][2] = {{0.f, 0.f}, {0.f, 0.f}};

    for (int kt = 0; kt < SEQ / 64; kt++) {
        const uint32_t kb = (uint32_t)(kt & 1) * KVBUF;
        if (kt + 1 < SEQ / 64) {
            const uint32_t nb = (uint32_t)((kt + 1) & 1) * KVBUF;
            const size_t t0 = (size_t)(kt + 1) * 64;
            const int row = tid >> 2, cc = (tid & 3) * 2;
#pragma unroll
            for (int i = 0; i < 2; i++) {
                const int c = cc + i;
                CP16(sb + A_KH + nb + row * PSTR + c * 16,
                     gKh + (t0 + row) * 128 + c * 16);
                CP16(sb + A_KL + nb + row * PSTR + c * 16,
                     gKl + (t0 + row) * 128 + c * 16);
                CP16(sb + A_VH + nb + row * PSTR + c * 16,
                     gVh + (size_t)row * (SEQ * 2) + t0 * 2 + c * 16);
                CP16(sb + A_VL + nb + row * PSTR + c * 16,
                     gVl + (size_t)row * (SEQ * 2) + t0 * 2 + c * 16);
            }
            CP_COMMIT();
            CP_WAIT1();
        } else {
            CP_WAIT0();
        }
        __syncthreads();

        float s[2][4][4];
#pragma unroll
        for (int mi = 0; mi < 2; mi++)
#pragma unroll
            for (int ni = 0; ni < 4; ni++)
#pragma unroll
                for (int j = 0; j < 4; j++) s[mi][ni][j] = 0.f;

#pragma unroll
        for (int src = 0; src < 3; src++) {
            const uint32_t aB = sb + (src == 1 ? A_QL : A_QH);
            const uint32_t bB = sb + (src == 2 ? A_KL : A_KH) + kb;
#pragma unroll
            for (int kc = 0; kc < 4; kc++) {
                const uint32_t ach = (uint32_t)((kc * 2 + ag2) * 16);
                const uint32_t bch = (uint32_t)((kc * 2 + bg2) * 16);
                uint32_t a[2][4];
#pragma unroll
                for (int mi = 0; mi < 2; mi++)
                    ldsm4(a[mi], aB + (uint32_t)((wm * 32 + mi * 16 + alr) * PSTR) + ach);
#pragma unroll
                for (int g = 0; g < 2; g++) {
                    uint32_t bf[4];
                    ldsm4(bf, bB + (uint32_t)((wn * 32 + g * 16 + nlr) * PSTR) + bch);
                    mma16816(s[0][2 * g + 0], a[0], bf[0], bf[1]);
                    mma16816(s[0][2 * g + 1], a[0], bf[2], bf[3]);
                    mma16816(s[1][2 * g + 0], a[1], bf[0], bf[1]);
                    mma16816(s[1][2 * g + 1], a[1], bf[2], bf[3]);
                }
            }
        }

#pragma unroll
        for (int mi = 0; mi < 2; mi++) {
#pragma unroll
            for (int ni = 0; ni < 4; ni++) {
                float p0 = __expf(fminf(s[mi][ni][0] * 0.125f, 80.f));
                float p1 = __expf(fminf(s[mi][ni][1] * 0.125f, 80.f));
                float p2 = __expf(fminf(s[mi][ni][2] * 0.125f, 80.f));
                float p3 = __expf(fminf(s[mi][ni][3] * 0.125f, 80.f));
                ls[mi][0] += p0 + p1;
                ls[mi][1] += p2 + p3;
                __nv_bfloat162 lo01, lo23;
                __nv_bfloat162 hi01 = split_hi2(p0, p1, lo01);
                __nv_bfloat162 hi23 = split_hi2(p2, p3, lo23);
                const int r = wm * 32 + mi * 16 + (lane >> 2);
                const int c = wn * 32 + ni * 8 + (lane & 3) * 2;
                *(__nv_bfloat162*)(sm2 + A_PH + r * PSTR + c * 2) = hi01;
                *(__nv_bfloat162*)(sm2 + A_PH + (r + 8) * PSTR + c * 2) = hi23;
                *(__nv_bfloat162*)(sm2 + A_PL + r * PSTR + c * 2) = lo01;
                *(__nv_bfloat162*)(sm2 + A_PL + (r + 8) * PSTR + c * 2) = lo23;
            }
        }
        __syncthreads();

#pragma unroll
        for (int src = 0; src < 3; src++) {
            const uint32_t aB = sb + (src == 1 ? A_PL : A_PH);
            const uint32_t bB = sb + (src == 2 ? A_VL : A_VH) + kb;
#pragma unroll
            for (int kc = 0; kc < 4; kc++) {
                const uint32_t ach = (uint32_t)((kc * 2 + ag2) * 16);
                const uint32_t bch = (uint32_t)((kc * 2 + bg2) * 16);
                uint32_t a[2][4];
#pragma unroll
                for (int mi = 0; mi < 2; mi++)
                    ldsm4(a[mi], aB + (uint32_t)((wm * 32 + mi * 16 + alr) * PSTR) + ach);
#pragma unroll
                for (int g = 0; g < 2; g++) {
                    uint32_t bf[4];
                    ldsm4(bf, bB + (uint32_t)((wn * 32 + g * 16 + nlr) * PSTR) + bch);
                    mma16816(o[0][2 * g + 0], a[0], bf[0], bf[1]);
                    mma16816(o[0][2 * g + 1], a[0], bf[2], bf[3]);
                    mma16816(o[1][2 * g + 0], a[1], bf[0], bf[1]);
                    mma16816(o[1][2 * g + 1], a[1], bf[2], bf[3]);
                }
            }
        }
    }

    // ---- epilogue: reduce row sums, normalize, write g_AY [hi|lo] ----
#pragma unroll
    for (int mi = 0; mi < 2; mi++) {
#pragma unroll
        for (int hf = 0; hf < 2; hf++) {
            float v = ls[mi][hf];
            v += __shfl_xor_sync(0xffffffffu, v, 1);
            v += __shfl_xor_sync(0xffffffffu, v, 2);
            if ((lane & 3) == 0)
                LS[wn * 128 + wm * 32 + mi * 16 + (lane >> 2) + hf * 8] = v;
        }
    }
    __syncthreads();
#pragma unroll
    for (int mi = 0; mi < 2; mi++) {
#pragma unroll
        for (int hf = 0; hf < 2; hf++) {
            const int r = wm * 32 + mi * 16 + (lane >> 2) + hf * 8;
            const float linv = 1.0f / (LS[r] + LS[128 + r]);
            const size_t rowbase = (size_t)(b * SEQ + q0 + r) * K2;
#pragma unroll
            for (int ni = 0; ni < 4; ni++) {
                const int c = wn * 32 + ni * 8 + (lane & 3) * 2;
                const float y0 = o[mi][ni][hf * 2] * linv;
                const float y1 = o[mi][ni][hf * 2 + 1] * linv;
                __nv_bfloat162 lo2;
                __nv_bfloat162 hi2 = split_hi2(y0, y1, lo2);
                const int kc = h * 64 + c;
                *(__nv_bfloat162*)&g_AY[rowbase + kc] = hi2;
                *(__nv_bfloat162*)&g_AY[rowbase + DM + kc] = lo2;
            }
        }
    }
}

// ---------------------------------------------------------------------------
// Launch: 8 kernels total
// ---------------------------------------------------------------------------
extern "C" void kernel_launch(void* const* d_in, const int* in_sizes, int n_in,
                              void* d_out, int out_size) {
    const float* q  = (const float*)d_in[0];
    const float* k  = (const float*)d_in[1];
    const float* v  = (const float*)d_in[2];
    const float* Wq = (const float*)d_in[3];
    const float* Wk = (const float*)d_in[4];
    const float* Wv = (const float*)d_in[5];
    const float* Wo = (const float*)d_in[6];
    const float* bo = (const float*)d_in[7];
    float* out = (float*)d_out;

    cudaFuncSetAttribute(attn2_kernel,
                         cudaFuncAttributeMaxDynamicSharedMemorySize, ATTN_SMEM2);
    cudaFuncSetAttribute(gemm_qkv_kernel,
                         cudaFuncAttributeMaxDynamicSharedMemorySize, GEMM_SMEM);
    cudaFuncSetAttribute(gemm_out_kernel,
                         cudaFuncAttributeMaxDynamicSharedMemorySize, GEMM_SMEM);

    theta_kernel<<<1, 512>>>();
    table_kernel<<<(SEQ * NP) / 256, 256>>>();

    split_w4_kernel<<<dim3(DM * DM / 256, 4), 256>>>(Wq, Wk, Wv, Wo);
    split_a3_kernel<<<dim3(RR * DM / 256, 3), 256>>>(q, k, v);

    gemm_qkv_kernel<<<dim3(DM / 128, RR / 128, 3), 256, GEMM_SMEM>>>();

    v_prep_kernel<<<dim3(SEQ / 32, DM / 32, BSZ), dim3(32, 8)>>>();

    attn2_kernel<<<dim3(SEQ / 128, BSZ * HN), 256, ATTN_SMEM2>>>();

    gemm_out_kernel<<<dim3(DM / 128, RR / 128), 256, GEMM_SMEM>>>(bo, out);
}

// round 11
// speedup vs baseline: 1.0097x; 1.0097x over previous
#include <cuda_runtime.h>
#include <cuda_bf16.h>
#include <cuda_fp8.h>
#include <math.h>
#include <stdint.h>

typedef unsigned long long ull;

#define BSZ 2
#define SEQ 2048
#define DM  1024
#define HN  16
#define DKH 64
#define RR  (BSZ*SEQ)   // 4096 rows
#define NP  (DM/2)      // 512 rotary pairs
// unified operand row stride: 2048 bytes (1024 bf16 OR 2048 fp8)
#define ROWB 2048

// ---------------------------------------------------------------------------
// Scratch (device globals: allocation is forbidden)
// ---------------------------------------------------------------------------
__device__ float g_V[RR*DM];
__device__ float g_theta[NP];
__device__ float g_cos[SEQ*NP];
__device__ float g_sin[SEQ*NP];
__device__ __nv_bfloat16 g_A3h[3*RR*DM];      // q,k,v: Ahi bf16 [row][1024]
__device__ unsigned char  g_A8[3*RR*2*DM];    // q,k,v: [Ahi | Alo*2^9] e4m3 [row][2048]
__device__ __nv_bfloat16 g_W4h[4*DM*DM];      // W*: Whi bf16 [col][1024]
__device__ unsigned char  g_W8[4*DM*2*DM];    // W*: [Wlo*2^14 | Whi*2^5] e4m3 [col][2048]
__device__ __nv_bfloat16 g_AYh[RR*DM];        // attn out: hi bf16
__device__ unsigned char  g_AY8[RR*2*DM];     // attn out: [yhi | ylo*2^9] e4m3
// attention operands: [bh][s][64] (Q/K) and [bh][d][s] (V transposed)
__device__ __nv_bfloat16 g_Qh[BSZ*HN*SEQ*DKH];
__device__ __nv_bfloat16 g_Ql[BSZ*HN*SEQ*DKH];
__device__ __nv_bfloat16 g_Kh[BSZ*HN*SEQ*DKH];
__device__ __nv_bfloat16 g_Kl[BSZ*HN*SEQ*DKH];
__device__ __nv_bfloat16 g_Vth[BSZ*HN*DKH*SEQ];
__device__ __nv_bfloat16 g_Vtl[BSZ*HN*DKH*SEQ];

// ---------------------------------------------------------------------------
// PTX helpers
// ---------------------------------------------------------------------------
static __device__ __forceinline__ uint32_t smem_u32(const void* p) {
    uint32_t a;
    asm("{ .reg .u64 t; cvta.to.shared.u64 t, %1; cvt.u32.u64 %0, t; }"
        : "=r"(a) : "l"(p));
    return a;
}
#define CP16(dst, src) \
    asm volatile("cp.async.cg.shared.global [%0], [%1], 16;" \
                 :: "r"(dst), "l"(src) : "memory")
#define CP_COMMIT() asm volatile("cp.async.commit_group;" ::: "memory")
#define CP_WAIT0()  asm volatile("cp.async.wait_group 0;" ::: "memory")
#define CP_WAIT1()  asm volatile("cp.async.wait_group 1;" ::: "memory")

static __device__ __forceinline__ void ldsm4(uint32_t* r, uint32_t addr) {
    asm volatile("ldmatrix.sync.aligned.m8n8.x4.shared.b16 {%0,%1,%2,%3}, [%4];"
                 : "=r"(r[0]), "=r"(r[1]), "=r"(r[2]), "=r"(r[3]) : "r"(addr));
}
static __device__ __forceinline__ void mma16816(float* c, const uint32_t* a,
                                                uint32_t b0, uint32_t b1) {
    asm volatile(
        "mma.sync.aligned.m16n8k16.row.col.f32.bf16.bf16.f32 "
        "{%0,%1,%2,%3}, {%4,%5,%6,%7}, {%8,%9}, {%0,%1,%2,%3};"
        : "+f"(c[0]), "+f"(c[1]), "+f"(c[2]), "+f"(c[3])
        : "r"(a[0]), "r"(a[1]), "r"(a[2]), "r"(a[3]), "r"(b0), "r"(b1));
}
// fp8 e4m3 mma, k32 — fragment layout byte-identical to bf16 k16
static __device__ __forceinline__ void mma16832f8(float* c, const uint32_t* a,
                                                  uint32_t b0, uint32_t b1) {
    asm volatile(
        "mma.sync.aligned.m16n8k32.row.col.f32.e4m3.e4m3.f32 "
        "{%0,%1,%2,%3}, {%4,%5,%6,%7}, {%8,%9}, {%0,%1,%2,%3};"
        : "+f"(c[0]), "+f"(c[1]), "+f"(c[2]), "+f"(c[3])
        : "r"(a[0]), "r"(a[1]), "r"(a[2]), "r"(a[3]), "r"(b0), "r"(b1));
}
static __device__ __forceinline__ __nv_bfloat162 split_hi2(float x, float y,
                                                           __nv_bfloat162& lo) {
    __nv_bfloat16 hx = __float2bfloat16(x), hy = __float2bfloat16(y);
    lo = __nv_bfloat162{__float2bfloat16(x - __bfloat162float(hx)),
                        __float2bfloat16(y - __bfloat162float(hy))};
    return __nv_bfloat162{hx, hy};
}
static __device__ __forceinline__ uint16_t f2e4m3x2(float x, float y) {
    uint16_t lo = (uint16_t)__nv_cvt_float_to_fp8(x, __NV_SATFINITE, __NV_E4M3);
    uint16_t hi = (uint16_t)__nv_cvt_float_to_fp8(y, __NV_SATFINITE, __NV_E4M3);
    return (uint16_t)(lo | (hi << 8));
}

// ---------------------------------------------------------------------------
// RoPE tables
// ---------------------------------------------------------------------------
__global__ void theta_kernel() {
    int i = threadIdx.x;
    if (i < NP)
        g_theta[i] = (float)pow(10000.0, -2.0 * (double)i / (double)DM);
}

__global__ void __launch_bounds__(256) table_kernel() {
    int idx = blockIdx.x * 256 + threadIdx.x;
    if (idx < SEQ * NP) {
        int pos = idx >> 9;
        int i   = idx & (NP - 1);
        float ang = (float)pos * g_theta[i];
        float s, c;
        sincosf(ang, &s, &c);
        g_cos[idx] = c;
        g_sin[idx] = s;
    }
}

// ---------------------------------------------------------------------------
// Splits: bf16 hi + e4m3 correction operands (2 elements per thread)
// A: Ahi bf16; A8 = [e4m3(x) | e4m3(lo*512)]
// W: Whi bf16; W8 = [e4m3(lo*16384) | e4m3(hi*32)]
// ---------------------------------------------------------------------------
__global__ void __launch_bounds__(256) split_a3_kernel(
    const float* __restrict__ q, const float* __restrict__ k,
    const float* __restrict__ v) {
    int idx = blockIdx.x * 256 + threadIdx.x;     // element-pair index
    const float* X = blockIdx.y == 0 ? q : (blockIdx.y == 1 ? k : v);
    int row = idx >> 9, kk = (idx & 511) * 2;
    float2 x2 = *(const float2*)&X[(size_t)row * DM + kk];
    __nv_bfloat162 lo2;
    __nv_bfloat162 hi2 = split_hi2(x2.x, x2.y, lo2);
    __nv_bfloat16* Oh = g_A3h + (size_t)blockIdx.y * (RR * DM);
    unsigned char* O8 = g_A8 + (size_t)blockIdx.y * (RR * 2 * DM);
    *(__nv_bfloat162*)&Oh[(size_t)row * DM + kk] = hi2;
    size_t b8 = (size_t)row * (2 * DM);
    *(uint16_t*)&O8[b8 + kk] = f2e4m3x2(x2.x, x2.y);
    *(uint16_t*)&O8[b8 + DM + kk] =
        f2e4m3x2(__bfloat162float(lo2.x) * 512.f, __bfloat162float(lo2.y) * 512.f);
}

__global__ void __launch_bounds__(256) split_w4_kernel(
    const float* __restrict__ Wq, const float* __restrict__ Wk,
    const float* __restrict__ Wv, const float* __restrict__ Wo) {
    int idx = blockIdx.x * 256 + threadIdx.x;
    const float* X = blockIdx.y == 0 ? Wq :
                     (blockIdx.y == 1 ? Wk : (blockIdx.y == 2 ? Wv : Wo));
    int row = idx >> 9, kk = (idx & 511) * 2;
    float2 x2 = *(const float2*)&X[(size_t)row * DM + kk];
    __nv_bfloat162 lo2;
    __nv_bfloat162 hi2 = split_hi2(x2.x, x2.y, lo2);
    __nv_bfloat16* Oh = g_W4h + (size_t)blockIdx.y * (DM * DM);
    unsigned char* O8 = g_W8 + (size_t)blockIdx.y * (DM * 2 * DM);
    *(__nv_bfloat162*)&Oh[(size_t)row * DM + kk] = hi2;
    size_t b8 = (size_t)row * (2 * DM);
    *(uint16_t*)&O8[b8 + kk] =
        f2e4m3x2(__bfloat162float(lo2.x) * 16384.f, __bfloat162float(lo2.y) * 16384.f);
    *(uint16_t*)&O8[b8 + DM + kk] =
        f2e4m3x2(__bfloat162float(hi2.x) * 32.f, __bfloat162float(hi2.y) * 32.f);
}

// V: transpose + split into [bh][d][s]
__global__ void __launch_bounds__(256) v_prep_kernel() {
    __shared__ float t[32][33];
    int s0 = blockIdx.x * 32, d0 = blockIdx.y * 32, b = blockIdx.z;
    int tx = threadIdx.x, ty = threadIdx.y;   // block (32, 8)
#pragma unroll
    for (int r = 0; r < 4; r++) {
        int sl = ty + r * 8;
        t[sl][tx] = g_V[(size_t)(b * SEQ + s0 + sl) * DM + d0 + tx];
    }
    __syncthreads();
    int head = d0 >> 6;
    int bh = b * HN + head;
#pragma unroll
    for (int r = 0; r < 4; r++) {
        int dl = ty + r * 8;
        float x = t[tx][dl];
        __nv_bfloat16 hi = __float2bfloat16(x);
        __nv_bfloat16 lo = __float2bfloat16(x - __bfloat162float(hi));
        size_t o = ((size_t)bh * 64 + ((d0 & 63) + dl)) * SEQ + s0 + tx;
        g_Vth[o] = hi;
        g_Vtl[o] = lo;
    }
}

// ---------------------------------------------------------------------------
// HMMA GEMM: phase 1 = fp8 corrections (K=2048 e4m3, scale 2^14), then
// acc *= 2^-14, phase 2 = bf16 main (K=1024). 128x128 tile, 8 warps,
// 128B k-chunks, 3-stage cp.async pipeline (R10-validated skeleton).
// ---------------------------------------------------------------------------
#define NKIT 32                 // 16 fp8 tiles + 16 bf16 tiles
#define STAGE_A 16384           // 128 rows x 128 B
#define STAGE_SZ (2 * STAGE_A)  // A + B
#define GEMM_SMEM (3 * STAGE_SZ)

static __device__ __forceinline__ void gemm_mainloop(
    const char* A8, const char* Ah, const char* W8, const char* Wh,
    char* sm, int row0, int col0, float acc[2][8][4]) {
    const uint32_t sb = smem_u32(sm);
    const int tid = threadIdx.x;
    const int lane = tid & 31, wid = tid >> 5;
    const int wm = wid & 3, wn = wid >> 2;

    // global->smem: thread loads row lr, 4 chunks starting at c0
    const int lr = tid >> 1;
    const int c0 = (tid & 1) * 4;
    const int ssel = lr & 7;
    const char* AgF = A8 + (size_t)(row0 + lr) * ROWB;
    const char* AgH = Ah + (size_t)(row0 + lr) * ROWB;
    const char* WgF = W8 + (size_t)(col0 + lr) * ROWB;
    const char* WgH = Wh + (size_t)(col0 + lr) * ROWB;
    uint32_t sdA[4], sdB[4];
#pragma unroll
    for (int i = 0; i < 4; i++) {
        sdA[i] = sb + (uint32_t)(lr * 128 + (((c0 + i) ^ ssel) * 16));
        sdB[i] = sdA[i] + STAGE_A;
    }

    // ldmatrix lane components
    const int alr = (lane & 7) + ((lane >> 3) & 1) * 8;
    const int ag2 = lane >> 4;
    const int asel = alr & 7;
    const int nlr = (lane & 7) + ((lane >> 4) & 1) * 8;
    const int bg2 = (lane >> 3) & 1;
    const int bsel = nlr & 7;

    uint32_t arow[2], brow[4];
#pragma unroll
    for (int mi = 0; mi < 2; mi++)
        arow[mi] = (uint32_t)((wm * 32 + mi * 16 + alr) * 128);
#pragma unroll
    for (int nj = 0; nj < 4; nj++)
        brow[nj] = (uint32_t)(STAGE_A + (wn * 64 + nj * 16 + nlr) * 128);

#pragma unroll
    for (int mi = 0; mi < 2; mi++)
#pragma unroll
        for (int ni = 0; ni < 8; ni++)
#pragma unroll
            for (int j = 0; j < 4; j++) acc[mi][ni][j] = 0.f;

    // prologue: stage kt=0,1 (both fp8 phase)
#pragma unroll
    for (int p = 0; p < 2; p++) {
        const uint32_t stb = (uint32_t)p * STAGE_SZ;
#pragma unroll
        for (int i = 0; i < 4; i++) {
            CP16(sdA[i] + stb, AgF + p * 128 + (c0 + i) * 16);
            CP16(sdB[i] + stb, WgF + p * 128 + (c0 + i) * 16);
        }
        CP_COMMIT();
    }

    int st = 0;
    for (int kt = 0; kt < NKIT; kt++) {
        if (kt == NKIT - 1) CP_WAIT0(); else CP_WAIT1();
        __syncthreads();
        if (kt + 2 < NKIT) {
            int stn = st + 2; if (stn >= 3) stn -= 3;
            const uint32_t stb = (uint32_t)stn * STAGE_SZ;
            const int ktp = kt + 2;
            const char* sA = ktp < 16 ? AgF + ktp * 128 : AgH + (ktp - 16) * 128;
            const char* sW = ktp < 16 ? WgF + ktp * 128 : WgH + (ktp - 16) * 128;
#pragma unroll
            for (int i = 0; i < 4; i++) {
                CP16(sdA[i] + stb, sA + (c0 + i) * 16);
                CP16(sdB[i] + stb, sW + (c0 + i) * 16);
            }
            CP_COMMIT();
        }
        if (kt == 16) {   // fp8 corrections done: undo 2^14 operand scaling
            const float s = 1.f / 16384.f;
#pragma unroll
            for (int mi = 0; mi < 2; mi++)
#pragma unroll
                for (int ni = 0; ni < 8; ni++)
#pragma unroll
                    for (int j = 0; j < 4; j++) acc[mi][ni][j] *= s;
        }
        const uint32_t stb = sb + (uint32_t)st * STAGE_SZ;
        if (kt < 16) {
#pragma unroll
            for (int ks = 0; ks < 4; ks++) {
                const uint32_t acs = (uint32_t)(((ks * 2 + ag2) ^ asel) * 16);
                const uint32_t bcs = (uint32_t)(((ks * 2 + bg2) ^ bsel) * 16);
                uint32_t a[2][4];
#pragma unroll
                for (int mi = 0; mi < 2; mi++)
                    ldsm4(a[mi], stb + arow[mi] + acs);
#pragma unroll
                for (int nj = 0; nj < 4; nj++) {
                    uint32_t b[4];
                    ldsm4(b, stb + brow[nj] + bcs);
                    mma16832f8(acc[0][2 * nj + 0], a[0], b[0], b[1]);
                    mma16832f8(acc[0][2 * nj + 1], a[0], b[2], b[3]);
                    mma16832f8(acc[1][2 * nj + 0], a[1], b[0], b[1]);
                    mma16832f8(acc[1][2 * nj + 1], a[1], b[2], b[3]);
                }
            }
        } else {
#pragma unroll
            for (int ks = 0; ks < 4; ks++) {
                const uint32_t acs = (uint32_t)(((ks * 2 + ag2) ^ asel) * 16);
                const uint32_t bcs = (uint32_t)(((ks * 2 + bg2) ^ bsel) * 16);
                uint32_t a[2][4];
#pragma unroll
                for (int mi = 0; mi < 2; mi++)
                    ldsm4(a[mi], stb + arow[mi] + acs);
#pragma unroll
                for (int nj = 0; nj < 4; nj++) {
                    uint32_t b[4];
                    ldsm4(b, stb + brow[nj] + bcs);
                    mma16816(acc[0][2 * nj + 0], a[0], b[0], b[1]);
                    mma16816(acc[0][2 * nj + 1], a[0], b[2], b[3]);
                    mma16816(acc[1][2 * nj + 0], a[1], b[0], b[1]);
                    mma16816(acc[1][2 * nj + 1], a[1], b[2], b[3]);
                }
            }
        }
        if (++st >= 3) st = 0;
    }
    __syncthreads();
}

__global__ void __launch_bounds__(256, 2) gemm_qkv_kernel() {
    extern __shared__ __align__(16) char smg[];
    const int z = blockIdx.z;
    const int row0 = blockIdx.y * 128, col0 = blockIdx.x * 128;
    const char* A8 = (const char*)g_A8 + (size_t)z * (RR * 2 * DM);
    const char* Ah = (const char*)g_A3h + (size_t)z * (RR * DM) * 2;
    const char* W8 = (const char*)g_W8 + (size_t)z * (DM * 2 * DM);
    const char* Wh = (const char*)g_W4h + (size_t)z * (DM * DM) * 2;

    float acc[2][8][4];
    gemm_mainloop(A8, Ah, W8, Wh, smg, row0, col0, acc);

    const int lane = threadIdx.x & 31, wid = threadIdx.x >> 5;
    const int wm = wid & 3, wn = wid >> 2;
    const int rbase = row0 + wm * 32 + (lane >> 2);
    const int cbase = col0 + wn * 64 + (lane & 3) * 2;

    if (z == 2) {   // V: plain fp32
#pragma unroll
        for (int mi = 0; mi < 2; mi++)
#pragma unroll
            for (int ni = 0; ni < 8; ni++) {
                const int r = rbase + mi * 16;
                const int c = cbase + ni * 8;
                *(float2*)&g_V[(size_t)r * DM + c] =
                    make_float2(acc[mi][ni][0], acc[mi][ni][1]);
                *(float2*)&g_V[(size_t)(r + 8) * DM + c] =
                    make_float2(acc[mi][ni][2], acc[mi][ni][3]);
            }
        return;
    }

    // Q/K: fused RoPE + hi/lo split into per-head layout
    __nv_bfloat16* Oh = z ? g_Kh : g_Qh;
    __nv_bfloat16* Ol = z ? g_Kl : g_Ql;
#pragma unroll
    for (int mi = 0; mi < 2; mi++) {
#pragma unroll
        for (int ni = 0; ni < 8; ni++) {
            const int c = cbase + ni * 8;       // even
            const int p = c >> 1;
            const int head = c >> 6, coff = c & 63;
#pragma unroll
            for (int hf = 0; hf < 2; hf++) {
                const int grow = rbase + mi * 16 + hf * 8;
                const int bb = grow >> 11, spos = grow & (SEQ - 1);
                const float cv = g_cos[spos * NP + p];
                const float sv = g_sin[spos * NP + p];
                const float x0 = acc[mi][ni][hf * 2];
                const float x1 = acc[mi][ni][hf * 2 + 1];
                const float ox = x0 * cv + x1 * sv;
                const float oy = x1 * cv - x0 * sv;
                __nv_bfloat162 lo2;
                __nv_bfloat162 hi2 = split_hi2(ox, oy, lo2);
                const size_t off =
                    ((size_t)(bb * HN + head) * SEQ + spos) * 64 + coff;
                *(__nv_bfloat162*)&Oh[off] = hi2;
                *(__nv_bfloat162*)&Ol[off] = lo2;
            }
        }
    }
}

__global__ void __launch_bounds__(256, 2) gemm_out_kernel(
    const float* __restrict__ bias, float* __restrict__ C) {
    extern __shared__ __align__(16) char smg[];
    const int row0 = blockIdx.y * 128, col0 = blockIdx.x * 128;
    const char* W8 = (const char*)g_W8 + (size_t)3 * (DM * 2 * DM);
    const char* Wh = (const char*)g_W4h + (size_t)3 * (DM * DM) * 2;

    float acc[2][8][4];
    gemm_mainloop((const char*)g_AY8, (const char*)g_AYh, W8, Wh,
                  smg, row0, col0, acc);

    const int lane = threadIdx.x & 31, wid = threadIdx.x >> 5;
    const int wm = wid & 3, wn = wid >> 2;
    const int rbase = row0 + wm * 32 + (lane >> 2);
    const int cbase = col0 + wn * 64 + (lane & 3) * 2;
#pragma unroll
    for (int mi = 0; mi < 2; mi++)
#pragma unroll
        for (int ni = 0; ni < 8; ni++) {
            const int r = rbase + mi * 16;
            const int c = cbase + ni * 8;
            const float b0 = bias[c], b1 = bias[c + 1];
            *(float2*)&C[(size_t)r * DM + c] =
                make_float2(acc[mi][ni][0] + b0, acc[mi][ni][1] + b1);
            *(float2*)&C[(size_t)(r + 8) * DM + c] =
                make_float2(acc[mi][ni][2] + b0, acc[mi][ni][3] + b1);
        }
}

// ---------------------------------------------------------------------------
// HMMA flash attention (R8-validated mainloop); epilogue writes AYh/AY8.
// ---------------------------------------------------------------------------
#define PSTR 144
#define A_QH 0
#define A_QL (A_QH + 128*PSTR)
#define A_KH (A_QL + 128*PSTR)
#define A_KL (A_KH + 2*64*PSTR)
#define A_VH (A_KL + 2*64*PSTR)
#define A_VL (A_VH + 2*64*PSTR)
#define A_PH (A_VL + 2*64*PSTR)
#define A_PL (A_PH + 128*PSTR)
#define A_LS (A_PL + 128*PSTR)
#define ATTN_SMEM2 (A_LS + 2*128*4)
#define KVBUF (64*PSTR)

__global__ void __launch_bounds__(256) attn2_kernel() {
    extern __shared__ char sm2[];
    const uint32_t sb = smem_u32(sm2);
    float* LS = (float*)(sm2 + A_LS);

    const int tid = threadIdx.x;
    const int lane = tid & 31, wid = tid >> 5;
    const int wm = wid & 3, wn = wid >> 2;
    const int q0 = blockIdx.x * 128;
    const int bh = blockIdx.y;
    const int b = bh >> 4, h = bh & 15;

    const char* gQh = (const char*)g_Qh + ((size_t)bh * SEQ + q0) * 128;
    const char* gQl = (const char*)g_Ql + ((size_t)bh * SEQ + q0) * 128;
    const char* gKh = (const char*)g_Kh + (size_t)bh * SEQ * 128;
    const char* gKl = (const char*)g_Kl + (size_t)bh * SEQ * 128;
    const char* gVh = (const char*)g_Vth + (size_t)bh * 64 * (SEQ * 2);
    const char* gVl = (const char*)g_Vtl + (size_t)bh * 64 * (SEQ * 2);

    const int alr = (lane & 7) + ((lane >> 3) & 1) * 8;
    const int ag2 = lane >> 4;
    const int nlr = (lane & 7) + ((lane >> 4) & 1) * 8;
    const int bg2 = (lane >> 3) & 1;

    {
        const int row = tid >> 1, c0 = (tid & 1) * 4;
#pragma unroll
        for (int i = 0; i < 4; i++) {
            const int c = c0 + i;
            CP16(sb + A_QH + row * PSTR + c * 16, gQh + (size_t)row * 128 + c * 16);
            CP16(sb + A_QL + row * PSTR + c * 16, gQl + (size_t)row * 128 + c * 16);
        }
    }
    {
        const int row = tid >> 2, cc = (tid & 3) * 2;
#pragma unroll
        for (int i = 0; i < 2; i++) {
            const int c = cc + i;
            CP16(sb + A_KH + row * PSTR + c * 16, gKh + (size_t)row * 128 + c * 16);
            CP16(sb + A_KL + row * PSTR + c * 16, gKl + (size_t)row * 128 + c * 16);
            CP16(sb + A_VH + row * PSTR + c * 16, gVh + (size_t)row * (SEQ * 2) + c * 16);
            CP16(sb + A_VL + row * PSTR + c * 16, gVl + (size_t)row * (SEQ * 2) + c * 16);
        }
    }
    CP_COMMIT();

    float o[2][4][4];
#pragma unroll
    for (int mi = 0; mi < 2; mi++)
#pragma unroll
        for (int ni = 0; ni < 4; ni++)
#pragma unroll
            for (int j = 0; j < 4; j++) o[mi][ni][j] = 0.f;
    float ls[2][2] = {{0.f, 0.f}, {0.f, 0.f}};

    for (int kt = 0; kt < SEQ / 64; kt++) {
        const uint32_t kb = (uint32_t)(kt & 1) * KVBUF;
        if (kt + 1 < SEQ / 64) {
            const uint32_t nb = (uint32_t)((kt + 1) & 1) * KVBUF;
            const size_t t0 = (size_t)(kt + 1) * 64;
            const int row = tid >> 2, cc = (tid & 3) * 2;
#pragma unroll
            for (int i = 0; i < 2; i++) {
                const int c = cc + i;
                CP16(sb + A_KH + nb + row * PSTR + c * 16,
                     gKh + (t0 + row) * 128 + c * 16);
                CP16(sb + A_KL + nb + row * PSTR + c * 16,
                     gKl + (t0 + row) * 128 + c * 16);
                CP16(sb + A_VH + nb + row * PSTR + c * 16,
                     gVh + (size_t)row * (SEQ * 2) + t0 * 2 + c * 16);
                CP16(sb + A_VL + nb + row * PSTR + c * 16,
                     gVl + (size_t)row * (SEQ * 2) + t0 * 2 + c * 16);
            }
            CP_COMMIT();
            CP_WAIT1();
        } else {
            CP_WAIT0();
        }
        __syncthreads();

        float s[2][4][4];
#pragma unroll
        for (int mi = 0; mi < 2; mi++)
#pragma unroll
            for (int ni = 0; ni < 4; ni++)
#pragma unroll
                for (int j = 0; j < 4; j++) s[mi][ni][j] = 0.f;

#pragma unroll
        for (int src = 0; src < 3; src++) {
            const uint32_t aB = sb + (src == 1 ? A_QL : A_QH);
            const uint32_t bB = sb + (src == 2 ? A_KL : A_KH) + kb;
#pragma unroll
            for (int kc = 0; kc < 4; kc++) {
                const uint32_t ach = (uint32_t)((kc * 2 + ag2) * 16);
                const uint32_t bch = (uint32_t)((kc * 2 + bg2) * 16);
                uint32_t a[2][4];
#pragma unroll
                for (int mi = 0; mi < 2; mi++)
                    ldsm4(a[mi], aB + (uint32_t)((wm * 32 + mi * 16 + alr) * PSTR) + ach);
#pragma unroll
                for (int g = 0; g < 2; g++) {
                    uint32_t bf[4];
                    ldsm4(bf, bB + (uint32_t)((wn * 32 + g * 16 + nlr) * PSTR) + bch);
                    mma16816(s[0][2 * g + 0], a[0], bf[0], bf[1]);
                    mma16816(s[0][2 * g + 1], a[0], bf[2], bf[3]);
                    mma16816(s[1][2 * g + 0], a[1], bf[0], bf[1]);
                    mma16816(s[1][2 * g + 1], a[1], bf[2], bf[3]);
                }
            }
        }

#pragma unroll
        for (int mi = 0; mi < 2; mi++) {
#pragma unroll
            for (int ni = 0; ni < 4; ni++) {
                float p0 = __expf(fminf(s[mi][ni][0] * 0.125f, 80.f));
                float p1 = __expf(fminf(s[mi][ni][1] * 0.125f, 80.f));
                float p2 = __expf(fminf(s[mi][ni][2] * 0.125f, 80.f));
                float p3 = __expf(fminf(s[mi][ni][3] * 0.125f, 80.f));
                ls[mi][0] += p0 + p1;
                ls[mi][1] += p2 + p3;
                __nv_bfloat162 lo01, lo23;
                __nv_bfloat162 hi01 = split_hi2(p0, p1, lo01);
                __nv_bfloat162 hi23 = split_hi2(p2, p3, lo23);
                const int r = wm * 32 + mi * 16 + (lane >> 2);
                const int c = wn * 32 + ni * 8 + (lane & 3) * 2;
                *(__nv_bfloat162*)(sm2 + A_PH + r * PSTR + c * 2) = hi01;
                *(__nv_bfloat162*)(sm2 + A_PH + (r + 8) * PSTR + c * 2) = hi23;
                *(__nv_bfloat162*)(sm2 + A_PL + r * PSTR + c * 2) = lo01;
                *(__nv_bfloat162*)(sm2 + A_PL + (r + 8) * PSTR + c * 2) = lo23;
            }
        }
        __syncthreads();

#pragma unroll
        for (int src = 0; src < 3; src++) {
            const uint32_t aB = sb + (src == 1 ? A_PL : A_PH);
            const uint32_t bB = sb + (src == 2 ? A_VL : A_VH) + kb;
#pragma unroll
            for (int kc = 0; kc < 4; kc++) {
                const uint32_t ach = (uint32_t)((kc * 2 + ag2) * 16);
                const uint32_t bch = (uint32_t)((kc * 2 + bg2) * 16);
                uint32_t a[2][4];
#pragma unroll
                for (int mi = 0; mi < 2; mi++)
                    ldsm4(a[mi], aB + (uint32_t)((wm * 32 + mi * 16 + alr) * PSTR) + ach);
#pragma unroll
                for (int g = 0; g < 2; g++) {
                    uint32_t bf[4];
                    ldsm4(bf, bB + (uint32_t)((wn * 32 + g * 16 + nlr) * PSTR) + bch);
                    mma16816(o[0][2 * g + 0], a[0], bf[0], bf[1]);
                    mma16816(o[0][2 * g + 1], a[0], bf[2], bf[3]);
                    mma16816(o[1][2 * g + 0], a[1], bf[0], bf[1]);
                    mma16816(o[1][2 * g + 1], a[1], bf[2], bf[3]);
                }
            }
        }
    }

    // ---- epilogue: reduce row sums, normalize, write AYh (bf16) + AY8 (e4m3)
#pragma unroll
    for (int mi = 0; mi < 2; mi++) {
#pragma unroll
        for (int hf = 0; hf < 2; hf++) {
            float v = ls[mi][hf];
            v += __shfl_xor_sync(0xffffffffu, v, 1);
            v += __shfl_xor_sync(0xffffffffu, v, 2);
            if ((lane & 3) == 0)
                LS[wn * 128 + wm * 32 + mi * 16 + (lane >> 2) + hf * 8] = v;
        }
    }
    __syncthreads();
#pragma unroll
    for (int mi = 0; mi < 2; mi++) {
#pragma unroll
        for (int hf = 0; hf < 2; hf++) {
            const int r = wm * 32 + mi * 16 + (lane >> 2) + hf * 8;
            const float linv = 1.0f / (LS[r] + LS[128 + r]);
            const size_t grow = (size_t)(b * SEQ + q0 + r);
#pragma unroll
            for (int ni = 0; ni < 4; ni++) {
                const int c = wn * 32 + ni * 8 + (lane & 3) * 2;
                const float y0 = o[mi][ni][hf * 2] * linv;
                const float y1 = o[mi][ni][hf * 2 + 1] * linv;
                __nv_bfloat162 lo2;
                __nv_bfloat162 hi2 = split_hi2(y0, y1, lo2);
                const int kc = h * 64 + c;
                *(__nv_bfloat162*)&g_AYh[grow * DM + kc] = hi2;
                *(uint16_t*)&g_AY8[grow * (2 * DM) + kc] = f2e4m3x2(y0, y1);
                *(uint16_t*)&g_AY8[grow * (2 * DM) + DM + kc] =
                    f2e4m3x2(__bfloat162float(lo2.x) * 512.f,
                             __bfloat162float(lo2.y) * 512.f);
            }
        }
    }
}

// ---------------------------------------------------------------------------
// Launch: 8 kernels total
// ---------------------------------------------------------------------------
extern "C" void kernel_launch(void* const* d_in, const int* in_sizes, int n_in,
                              void* d_out, int out_size) {
    const float* q  = (const float*)d_in[0];
    const float* k  = (const float*)d_in[1];
    const float* v  = (const float*)d_in[2];
    const float* Wq = (const float*)d_in[3];
    const float* Wk = (const float*)d_in[4];
    const float* Wv = (const float*)d_in[5];
    const float* Wo = (const float*)d_in[6];
    const float* bo = (const float*)d_in[7];
    float* out = (float*)d_out;

    cudaFuncSetAttribute(attn2_kernel,
                         cudaFuncAttributeMaxDynamicSharedMemorySize, ATTN_SMEM2);
    cudaFuncSetAttribute(gemm_qkv_kernel,
                         cudaFuncAttributeMaxDynamicSharedMemorySize, GEMM_SMEM);
    cudaFuncSetAttribute(gemm_out_kernel,
                         cudaFuncAttributeMaxDynamicSharedMemorySize, GEMM_SMEM);

    theta_kernel<<<1, 512>>>();
    table_kernel<<<(SEQ * NP) / 256, 256>>>();

    split_w4_kernel<<<dim3(DM * DM / 512, 4), 256>>>(Wq, Wk, Wv, Wo);
    split_a3_kernel<<<dim3(RR * DM / 512, 3), 256>>>(q, k, v);

    gemm_qkv_kernel<<<dim3(DM / 128, RR / 128, 3), 256, GEMM_SMEM>>>();

    v_prep_kernel<<<dim3(SEQ / 32, DM / 32, BSZ), dim3(32, 8)>>>();

    attn2_kernel<<<dim3(SEQ / 128, BSZ * HN), 256, ATTN_SMEM2>>>();

    gemm_out_kernel<<<dim3(DM / 128, RR / 128), 256, GEMM_SMEM>>>(bo, out);
}